// round 17
// baseline (speedup 1.0000x reference)
#include <cuda_runtime.h>
#include <cuda_fp16.h>
#include <cstdint>

// ============================================================================
// S6 forward, reduced:
//   y[t,d] = x[t,d] * softplus(U1[t,d] + b1[d]) * s[t]
//   s[t]   = sum_n (U2[t,n]+b2[n]) * (U3[t,n]+b3[n])
// Pipeline (fp16 mma.sync, fp32 accum; base sm_103 ISA — no tcgen05):
//   1. prep+packW1 (ONE kernel, first launch):
//        blocks [0,512):   x->fp16 + s[t]; W2/W3 cp.async-staged as fp32,
//                          B fragments built with on-the-fly cvt (no pack_w23!)
//        blocks [512,768): W1 fp32->fp16 copy (overlapped)
//   2. gemm: 128x128 CTA, 4 warps @ 64x64, A ldmatrix / B ldmatrix.trans,
//            3-stage cp.async, fused epilogue -> y
// ============================================================================

#define NTOK   8192
#define DDIM   1024

#define BM     128
#define BN     128
#define BK     32
#define NKIT   (DDIM / BK)   // 32
#define GTHREADS 128         // 4 warps, 2x2 warp grid, 64x64 per warp

#define PITCH_H   40         // A smem row pitch (halves) = 80B
#define B_PITCH_H 136        // B smem row pitch (halves) = 272B; trans-ldm conflict-free
#define A_STAGE_H (BM * PITCH_H)               // 5120 halves
#define B_STAGE_H (BK * B_PITCH_H)             // 4352 halves
#define G_STAGE_H (A_STAGE_H + B_STAGE_H)      // 9472
#define STAGES    3
#define G_SMEM_BYTES (STAGES * G_STAGE_H * 2)  // 56832

#define PREP_BLOCKS 512
#define COPY_BLOCKS 256       // 262144 float4 / 1024 per block

__device__ __half g_W1h[(size_t)DDIM * DDIM];  // W1, [k][n], fp16, 2 MB
__device__ __half g_Xh[(size_t)NTOK * DDIM];   // x fp16, 16.8 MB
__device__ float  g_s[NTOK];

// ---------------------------------------------------------------------------
// helpers
// ---------------------------------------------------------------------------
__device__ __forceinline__ uint32_t smem_u32(const void* p) {
    uint32_t a;
    asm("{ .reg .u64 t; cvta.to.shared.u64 t, %1; cvt.u32.u64 %0, t; }" : "=r"(a) : "l"(p));
    return a;
}
__device__ __forceinline__ uint32_t h2_u32(__half2 h) {
    union { __half2 h; uint32_t u; } cvt;
    cvt.h = h;
    return cvt.u;
}
__device__ __forceinline__ void cp_async16(uint32_t dst, const void* src) {
    asm volatile("cp.async.cg.shared.global [%0], [%1], 16;" :: "r"(dst), "l"(src) : "memory");
}
__device__ __forceinline__ void cp_commit() {
    asm volatile("cp.async.commit_group;" ::: "memory");
}
template <int N>
__device__ __forceinline__ void cp_wait() {
    asm volatile("cp.async.wait_group %0;" :: "n"(N) : "memory");
}
__device__ __forceinline__ void ldmx4(uint32_t* r, uint32_t addr) {
    asm volatile("ldmatrix.sync.aligned.m8n8.x4.shared.b16 {%0,%1,%2,%3}, [%4];"
        : "=r"(r[0]), "=r"(r[1]), "=r"(r[2]), "=r"(r[3]) : "r"(addr));
}
__device__ __forceinline__ void ldmx4t(uint32_t* r, uint32_t addr) {
    asm volatile("ldmatrix.sync.aligned.m8n8.x4.trans.shared.b16 {%0,%1,%2,%3}, [%4];"
        : "=r"(r[0]), "=r"(r[1]), "=r"(r[2]), "=r"(r[3]) : "r"(addr));
}
__device__ __forceinline__ void mma_f16(float* c, const uint32_t* a, const uint32_t* b) {
    asm volatile(
        "mma.sync.aligned.m16n8k16.row.col.f32.f16.f16.f32 "
        "{%0,%1,%2,%3}, {%4,%5,%6,%7}, {%8,%9}, {%0,%1,%2,%3};"
        : "+f"(c[0]), "+f"(c[1]), "+f"(c[2]), "+f"(c[3])
        : "r"(a[0]), "r"(a[1]), "r"(a[2]), "r"(a[3]), "r"(b[0]), "r"(b[1]));
}
__device__ __forceinline__ float softplus_f(float z) {
    return fmaxf(z, 0.0f) + __logf(1.0f + __expf(-fabsf(z)));
}

// ---------------------------------------------------------------------------
// Kernel 1: prep + W1 pack, one launch (the ONLY pre-GEMM kernel).
//   blocks [0,512):   x->fp16 convert + s[t], 16 tokens each;
//                     W2/W3 staged per-chunk as fp32 via cp.async
//   blocks [512,768): W1 fp32->fp16 copy, 4 float4 per thread
// ---------------------------------------------------------------------------
#define P_PITCH 136
#define PX_STG  (16 * P_PITCH)       // x stage: 2176 halves
#define PW_PITCH_F 36                // fp32 W staging pitch (144B, 16B-aligned rows)
#define PW_STG_F  (128 * PW_PITCH_F) // 4608 floats per stage

__global__ void __launch_bounds__(256) s6_prep(const float* __restrict__ x,
                                               const float* __restrict__ W1,
                                               const float* __restrict__ W2,
                                               const float* __restrict__ W3,
                                               const float* __restrict__ b2,
                                               const float* __restrict__ b3) {
    __shared__ __half sX[2][PX_STG];        // 8704 B
    __shared__ float  sWf[2][PW_STG_F];     // 36864 B
    __shared__ float  sU[16][33];           // 2112 B  -> total 47680 B (<48K)

    const int tid = threadIdx.x;

    if (blockIdx.x >= PREP_BLOCKS) {
        // ---- W1 copy path (overlaps prep blocks) ----
        const int rel = blockIdx.x - PREP_BLOCKS;
#pragma unroll
        for (int i = 0; i < 4; ++i) {
            const size_t i4 = (size_t)rel * 1024 + i * 256 + tid;
            const float4 v = ((const float4*)W1)[i4];
            uint2 pk;
            pk.x = h2_u32(__float22half2_rn(make_float2(v.x, v.y)));
            pk.y = h2_u32(__float22half2_rn(make_float2(v.z, v.w)));
            ((uint2*)g_W1h)[i4] = pk;
        }
        return;
    }

    // ---- prep path ----
    const int wid = tid >> 5;
    const int lane = tid & 31;
    const int grp = lane >> 2;
    const int qid = lane & 3;
    const int tok0 = blockIdx.x * 16;
    const uint32_t sWf_u[2] = { smem_u32(sWf[0]), smem_u32(sWf[1]) };

    for (int i = tid; i < 16 * 33; i += 256) ((float*)sU)[i] = 0.0f;

    // W chunk fill: 1024 x 16B chunks per chunk (4 per thread)
    //   idx: mat = idx>>9, k = (idx&511)>>2, nq = idx&3
    //   dst col = mat*16 + nq*4  (staging cols 0..15 = W2, 16..31 = W3)
#pragma unroll
    for (int j = 0; j < 4; ++j) {
        const int idx = tid + j * 256;
        const int mat = idx >> 9;
        const int r = idx & 511;
        const int k = r >> 2;
        const int nq = r & 3;
        cp_async16(sWf_u[0] + (uint32_t)(k * PW_PITCH_F + mat * 16 + nq * 4) * 4,
                   (mat ? W3 : W2) + (size_t)k * 16 + nq * 4);
    }
    cp_commit();

    const int t = tid >> 4;            // token row (0..15) for x convert
    const int co = (tid & 15) * 8;     // col offset within chunk

    float acc[4][4];
#pragma unroll
    for (int g = 0; g < 4; ++g)
#pragma unroll
        for (int q = 0; q < 4; ++q) acc[g][q] = 0.0f;

    for (int c = 0; c < 8; ++c) {
        const int st = c & 1;
        // ---- x chunk: load fp32, convert, store to sX + g_Xh ----
        const float* src = x + (size_t)(tok0 + t) * DDIM + c * 128 + co;
        float4 v0 = *(const float4*)(src + 0);
        float4 v1 = *(const float4*)(src + 4);
        uint4 pk;
        pk.x = h2_u32(__float22half2_rn(make_float2(v0.x, v0.y)));
        pk.y = h2_u32(__float22half2_rn(make_float2(v0.z, v0.w)));
        pk.z = h2_u32(__float22half2_rn(make_float2(v1.x, v1.y)));
        pk.w = h2_u32(__float22half2_rn(make_float2(v1.z, v1.w)));
        *(uint4*)(&sX[st][t * P_PITCH + co]) = pk;
        *(uint4*)(g_Xh + (size_t)(tok0 + t) * DDIM + c * 128 + co) = pk;

        cp_wait<0>();
        __syncthreads();   // sWf[st] ready, sX[st] visible, prior mma done

        if (c < 7) {       // prefetch next W chunk
            const int ns = (c + 1) & 1;
#pragma unroll
            for (int j = 0; j < 4; ++j) {
                const int idx = tid + j * 256;
                const int mat = idx >> 9;
                const int r = idx & 511;
                const int k = r >> 2;
                const int nq = r & 3;
                cp_async16(sWf_u[ns] + (uint32_t)(k * PW_PITCH_F + mat * 16 + nq * 4) * 4,
                           (mat ? W3 : W2) + (size_t)((c + 1) * 128 + k) * 16 + nq * 4);
            }
            cp_commit();
        }

        // ---- mma: warp `wid` handles k16 slice wid of the chunk; M=16, N=32
        const int koff = wid * 16 + 2 * qid;
        {
            const __half* p = &sX[st][grp * P_PITCH + koff];
            uint32_t a[4];
            a[0] = *(const uint32_t*)p;
            a[1] = *(const uint32_t*)(p + 8 * P_PITCH);
            a[2] = *(const uint32_t*)(p + 8);
            a[3] = *(const uint32_t*)(p + 8 * P_PITCH + 8);
            const float* wf = &sWf[st][koff * PW_PITCH_F];
#pragma unroll
            for (int g = 0; g < 4; ++g) {
                const int n = g * 8 + grp;
                uint32_t b[2];
                b[0] = h2_u32(__floats2half2_rn(wf[n], wf[PW_PITCH_F + n]));
                b[1] = h2_u32(__floats2half2_rn(wf[8 * PW_PITCH_F + n],
                                                wf[9 * PW_PITCH_F + n]));
                mma_f16(acc[g], a, b);
            }
        }
        __syncthreads();   // protect sX[st]/sWf[st] rewrite
    }

    // cross-warp reduce via smem atomics
#pragma unroll
    for (int g = 0; g < 4; ++g) {
        atomicAdd(&sU[grp][g * 8 + 2 * qid],         acc[g][0]);
        atomicAdd(&sU[grp][g * 8 + 2 * qid + 1],     acc[g][1]);
        atomicAdd(&sU[grp + 8][g * 8 + 2 * qid],     acc[g][2]);
        atomicAdd(&sU[grp + 8][g * 8 + 2 * qid + 1], acc[g][3]);
    }
    __syncthreads();

    if (tid < 16) {
        float s = 0.0f;
#pragma unroll
        for (int n = 0; n < 16; ++n)
            s += (sU[tid][n] + __ldg(b2 + n)) * (sU[tid][n + 16] + __ldg(b3 + n));
        g_s[tok0 + tid] = s;
    }
}

// ---------------------------------------------------------------------------
// Kernel 2: main GEMM — A ldmatrix from [m][k], B ldmatrix.trans from [k][n]
// ---------------------------------------------------------------------------
__device__ __forceinline__ void g_prefetch(uint32_t smem_base_u, int stage, int kt,
                                           int m0, int n0, int tid) {
    const uint32_t st = smem_base_u + (uint32_t)(stage * G_STAGE_H) * 2;
#pragma unroll
    for (int i = 0; i < 4; ++i) {           // A: 128 rows x 4 x 16B
        const int c = tid + i * GTHREADS;
        const int row = c >> 2, ch = c & 3;
        cp_async16(st + (uint32_t)(row * PITCH_H + ch * 8) * 2,
                   g_Xh + (size_t)(m0 + row) * DDIM + kt * BK + ch * 8);
    }
#pragma unroll
    for (int i = 0; i < 4; ++i) {           // B: 32 k-rows x 16 x 16B
        const int c = tid + i * GTHREADS;
        const int row = c >> 4, ch = c & 15;
        cp_async16(st + (uint32_t)(A_STAGE_H + row * B_PITCH_H + ch * 8) * 2,
                   g_W1h + (size_t)(kt * BK + row) * DDIM + n0 + ch * 8);
    }
}

__global__ void __launch_bounds__(GTHREADS, 2) s6_gemm(const float* __restrict__ x,
                                                       const float* __restrict__ b1,
                                                       float* __restrict__ y) {
    extern __shared__ __half smh[];
    const uint32_t sm_u = smem_u32(smh);

    const int tid = threadIdx.x;
    const int wid = tid >> 5;
    const int lane = tid & 31;
    const int grp = lane >> 2;
    const int qid = lane & 3;
    const int wm = wid & 1;      // 2 warps along M (64 each)
    const int wn = wid >> 1;     // 2 warps along N (64 each)
    const int m0 = blockIdx.y * BM;
    const int n0 = blockIdx.x * BN;

    const uint32_t aIdx = (uint32_t)((wm * 64 + (lane & 15)) * PITCH_H + (lane >> 4) * 8);
    const uint32_t bIdx = (uint32_t)(A_STAGE_H +
        (((lane >> 3) & 1) * 8 + (lane & 7)) * B_PITCH_H + ((lane >> 4) & 1) * 8 + wn * 64);

    float acc[4][8][4];
#pragma unroll
    for (int f = 0; f < 4; ++f)
#pragma unroll
        for (int g = 0; g < 8; ++g)
#pragma unroll
            for (int q = 0; q < 4; ++q) acc[f][g][q] = 0.0f;

    g_prefetch(sm_u, 0, 0, m0, n0, tid);
    cp_commit();
    g_prefetch(sm_u, 1, 1, m0, n0, tid);
    cp_commit();

    for (int kt = 0; kt < NKIT; ++kt) {
        const int s = kt % STAGES;
        cp_wait<1>();
        __syncthreads();

        const int pf = kt + 2;
        if (pf < NKIT) g_prefetch(sm_u, pf % STAGES, pf, m0, n0, tid);
        cp_commit();

        const uint32_t stg = sm_u + (uint32_t)(s * G_STAGE_H) * 2;
#pragma unroll
        for (int ks = 0; ks < 2; ++ks) {
            uint32_t af[4][4], bf[8][2];
#pragma unroll
            for (int f = 0; f < 4; ++f)
                ldmx4(af[f], stg + (aIdx + (uint32_t)(f * 16 * PITCH_H + ks * 16)) * 2);
#pragma unroll
            for (int h = 0; h < 4; ++h) {
                uint32_t bq[4];
                ldmx4t(bq, stg + (bIdx + (uint32_t)(ks * 16 * B_PITCH_H + h * 16)) * 2);
                bf[2 * h][0]     = bq[0];   // (k lo, n lo)
                bf[2 * h][1]     = bq[1];   // (k hi, n lo)
                bf[2 * h + 1][0] = bq[2];   // (k lo, n hi)
                bf[2 * h + 1][1] = bq[3];   // (k hi, n hi)
            }
#pragma unroll
            for (int f = 0; f < 4; ++f)
#pragma unroll
                for (int g = 0; g < 8; ++g)
                    mma_f16(acc[f][g], af[f], bf[g]);
        }
    }

    // fused epilogue: y = x * softplus(acc + b1) * s
#pragma unroll
    for (int f = 0; f < 4; ++f) {
        const int r0 = m0 + wm * 64 + f * 16 + grp;
        const int r1 = r0 + 8;
        const float s0 = __ldg(g_s + r0);
        const float s1 = __ldg(g_s + r1);
        const float* xr0 = x + (size_t)r0 * DDIM;
        const float* xr1 = x + (size_t)r1 * DDIM;
        float* yr0 = y + (size_t)r0 * DDIM;
        float* yr1 = y + (size_t)r1 * DDIM;
#pragma unroll
        for (int g = 0; g < 8; ++g) {
            const int c = n0 + wn * 64 + g * 8 + 2 * qid;
            const float2 bv = *(const float2*)(b1 + c);
            const float2 x0 = *(const float2*)(xr0 + c);
            const float2 x1 = *(const float2*)(xr1 + c);
            float2 o0, o1;
            o0.x = x0.x * softplus_f(acc[f][g][0] + bv.x) * s0;
            o0.y = x0.y * softplus_f(acc[f][g][1] + bv.y) * s0;
            o1.x = x1.x * softplus_f(acc[f][g][2] + bv.x) * s1;
            o1.y = x1.y * softplus_f(acc[f][g][3] + bv.y) * s1;
            *(float2*)(yr0 + c) = o0;
            *(float2*)(yr1 + c) = o1;
        }
    }
}

// ---------------------------------------------------------------------------
// Launch
// ---------------------------------------------------------------------------
extern "C" void kernel_launch(void* const* d_in, const int* in_sizes, int n_in,
                              void* d_out, int out_size) {
    const float* x  = (const float*)d_in[0];
    const float* W1 = (const float*)d_in[1];
    const float* b1 = (const float*)d_in[2];
    const float* W2 = (const float*)d_in[3];
    const float* b2 = (const float*)d_in[4];
    const float* W3 = (const float*)d_in[5];
    const float* b3 = (const float*)d_in[6];
    float* y = (float*)d_out;

    s6_prep<<<PREP_BLOCKS + COPY_BLOCKS, 256>>>(x, W1, W2, W3, b2, b3);

    cudaFuncSetAttribute(s6_gemm, cudaFuncAttributeMaxDynamicSharedMemorySize, G_SMEM_BYTES);
    s6_gemm<<<dim3(DDIM / BN, NTOK / BM), GTHREADS, G_SMEM_BYTES>>>(x, b1, y);
}